// round 8
// baseline (speedup 1.0000x reference)
#include <cuda_runtime.h>
#include <cuda_bf16.h>
#include <cstdint>

#define Bsz 4
#define Cch 256
#define Nsp 4096
#define Gg  32
#define CPG 8

// ---------------- scratch (static device memory; no allocations) ------------
__device__ __nv_bfloat16 g_s[Bsz * Cch * Nsp];   // [b][c][i]
__device__ __nv_bfloat16 g_q[Bsz * Nsp * Cch];   // [b][i][c] (scaled by C^-1/2)
__device__ __nv_bfloat16 g_k[Bsz * Nsp * Cch];   // [b][j][c]
__device__ __nv_bfloat16 g_v[Bsz * Cch * Nsp];   // [b][c][j]
__device__ __nv_bfloat16 g_h[Bsz * Nsp * Cch];   // [b][i][c]

// ---------------- helpers -----------------------------------------------------
__device__ __forceinline__ uint32_t smem_u32(const void* p) {
    uint32_t a;
    asm("{ .reg .u64 t; cvta.to.shared.u64 t, %1; cvt.u32.u64 %0, t; }" : "=r"(a) : "l"(p));
    return a;
}
__device__ __forceinline__ void mma_bf16(float* d, const uint32_t* a, const uint32_t* b) {
    asm volatile(
        "mma.sync.aligned.m16n8k16.row.col.f32.bf16.bf16.f32 "
        "{%0,%1,%2,%3}, {%4,%5,%6,%7}, {%8,%9}, {%0,%1,%2,%3};\n"
        : "+f"(d[0]), "+f"(d[1]), "+f"(d[2]), "+f"(d[3])
        : "r"(a[0]), "r"(a[1]), "r"(a[2]), "r"(a[3]), "r"(b[0]), "r"(b[1]));
}
__device__ __forceinline__ void mma2(float* d, const uint32_t* a, uint32_t b0, uint32_t b1) {
    asm volatile(
        "mma.sync.aligned.m16n8k16.row.col.f32.bf16.bf16.f32 "
        "{%0,%1,%2,%3}, {%4,%5,%6,%7}, {%8,%9}, {%0,%1,%2,%3};\n"
        : "+f"(d[0]), "+f"(d[1]), "+f"(d[2]), "+f"(d[3])
        : "r"(a[0]), "r"(a[1]), "r"(a[2]), "r"(a[3]), "r"(b0), "r"(b1));
}
__device__ __forceinline__ void ldsm4(uint32_t* r, uint32_t addr) {
    asm volatile("ldmatrix.sync.aligned.m8n8.x4.shared.b16 {%0,%1,%2,%3}, [%4];"
                 : "=r"(r[0]), "=r"(r[1]), "=r"(r[2]), "=r"(r[3]) : "r"(addr));
}
__device__ __forceinline__ void cp16(uint32_t saddr, const void* gaddr) {
    asm volatile("cp.async.cg.shared.global [%0], [%1], 16;" :: "r"(saddr), "l"(gaddr));
}
#define CP_COMMIT asm volatile("cp.async.commit_group;")
#define CP_WAIT(n) asm volatile("cp.async.wait_group %0;" :: "n"(n))
__device__ __forceinline__ float ex2(float a) {
    float d;
    asm("ex2.approx.ftz.f32 %0, %1;" : "=f"(d) : "f"(a));
    return d;
}

// ---------------- GroupNorm --> bf16 s ---------------------------------------
__global__ __launch_bounds__(256) void gn_kernel(const float* __restrict__ x,
                                                 const float* __restrict__ gamma,
                                                 const float* __restrict__ beta) {
    int bg = blockIdx.x;
    int b = bg >> 5;
    int g = bg & 31;
    const float4* xp = (const float4*)(x + ((size_t)b * Cch + g * CPG) * Nsp);
    const int total4 = CPG * Nsp / 4;

    float sum = 0.f, sq = 0.f;
    for (int i = threadIdx.x; i < total4; i += 256) {
        float4 v = xp[i];
        sum += v.x + v.y + v.z + v.w;
        sq  += v.x * v.x + v.y * v.y + v.z * v.z + v.w * v.w;
    }
    for (int off = 16; off > 0; off >>= 1) {
        sum += __shfl_xor_sync(0xffffffffu, sum, off);
        sq  += __shfl_xor_sync(0xffffffffu, sq, off);
    }
    __shared__ float ws[8], wq2[8];
    int warp = threadIdx.x >> 5, lane = threadIdx.x & 31;
    if (lane == 0) { ws[warp] = sum; wq2[warp] = sq; }
    __syncthreads();
    if (threadIdx.x == 0) {
        float s = 0.f, q = 0.f;
        for (int i = 0; i < 8; i++) { s += ws[i]; q += wq2[i]; }
        ws[0] = s; wq2[0] = q;
    }
    __syncthreads();
    const float invn = 1.0f / (float)(CPG * Nsp);
    float mean = ws[0] * invn;
    float var  = wq2[0] * invn - mean * mean;
    float rstd = rsqrtf(var + 1e-6f);

    __nv_bfloat162* sp = (__nv_bfloat162*)(g_s + ((size_t)b * Cch + g * CPG) * Nsp);
    for (int i = threadIdx.x; i < total4; i += 256) {
        float4 v = xp[i];
        int c = g * CPG + (i >> 10);
        float a  = rstd * gamma[c];
        float bb = beta[c] - mean * a;
        sp[2 * i]     = __floats2bfloat162_rn(v.x * a + bb, v.y * a + bb);
        sp[2 * i + 1] = __floats2bfloat162_rn(v.z * a + bb, v.w * a + bb);
    }
}

// ---------------- QKV 1x1 conv (bf16 HMMA GEMM, fused o-halves) --------------
// Each CTA: 128 i rows x ALL 256 o for one (w,b). Bs (strided s transpose)
// loaded once per k0 and reused for both o-halves.
// q,k written transposed: [b][i][c]; v kept [b][c][i]. q scaled by C^-1/2.
__global__ __launch_bounds__(256) void qkv_kernel(const float* __restrict__ wq,
                                                  const float* __restrict__ wk,
                                                  const float* __restrict__ wv,
                                                  const float* __restrict__ bq,
                                                  const float* __restrict__ bk,
                                                  const float* __restrict__ bv) {
    int z = blockIdx.z;
    int b = z & 3;
    int w = z >> 2;
    const float* W   = (w == 0) ? wq : (w == 1) ? wk : wv;
    const float* bia = (w == 0) ? bq : (w == 1) ? bk : bv;
    __nv_bfloat16* out = (w == 0) ? g_q : (w == 1) ? g_k : g_v;
    float scale = (w == 0) ? 0.0625f : 1.0f;

    int i0 = blockIdx.x * 128;

    __shared__ __align__(16) __nv_bfloat16 As[256][40];  // [o][c], all 256 o
    __shared__ __align__(16) __nv_bfloat16 Bs[128][40];  // [i][c]

    int tid = threadIdx.x, lane = tid & 31, warp = tid >> 5;
    int g = lane >> 2, t = lane & 3;
    int wm = warp & 3, wn = warp >> 2;

    float acc[2][2][8][4];
#pragma unroll
    for (int oh = 0; oh < 2; oh++)
#pragma unroll
        for (int mm = 0; mm < 2; mm++)
#pragma unroll
            for (int nn = 0; nn < 8; nn++)
#pragma unroll
                for (int r = 0; r < 4; r++) acc[oh][mm][nn][r] = 0.f;

    const __nv_bfloat16* sbase = g_s + (size_t)b * Cch * Nsp + i0;
    bool trans = (w < 2);   // q,k: D[i][o]; v: D[o][i]

    for (int k0 = 0; k0 < Cch; k0 += 32) {
#pragma unroll
        for (int idx = tid; idx < 256 * 32; idx += 256) {
            int r = idx >> 5, c = idx & 31;
            As[r][c] = __float2bfloat16_rn(W[(size_t)r * Cch + k0 + c]);
        }
#pragma unroll
        for (int idx = tid; idx < 32 * 64; idx += 256) {
            int c = idx >> 6, ip = idx & 63;
            uint32_t u = *(const uint32_t*)(sbase + (size_t)(k0 + c) * Nsp + 2 * ip);
            __nv_bfloat162 h2 = *reinterpret_cast<__nv_bfloat162*>(&u);
            Bs[2 * ip][c] = h2.x;
            Bs[2 * ip + 1][c] = h2.y;
        }
        __syncthreads();
#pragma unroll
        for (int oh = 0; oh < 2; oh++) {
            const __nv_bfloat16 (*Am)[40] = trans ? Bs : (As + oh * 128);
            const __nv_bfloat16 (*Bm)[40] = trans ? (As + oh * 128) : Bs;
#pragma unroll
            for (int kk = 0; kk < 32; kk += 16) {
                uint32_t a[2][4];
#pragma unroll
                for (int mm = 0; mm < 2; mm++) {
                    int r = wm * 32 + mm * 16;
                    a[mm][0] = *(const uint32_t*)&Am[r + g][kk + 2 * t];
                    a[mm][1] = *(const uint32_t*)&Am[r + g + 8][kk + 2 * t];
                    a[mm][2] = *(const uint32_t*)&Am[r + g][kk + 8 + 2 * t];
                    a[mm][3] = *(const uint32_t*)&Am[r + g + 8][kk + 8 + 2 * t];
                }
#pragma unroll
                for (int nn = 0; nn < 8; nn++) {
                    int nr = wn * 64 + nn * 8 + g;
                    uint32_t bb[2];
                    bb[0] = *(const uint32_t*)&Bm[nr][kk + 2 * t];
                    bb[1] = *(const uint32_t*)&Bm[nr][kk + 8 + 2 * t];
                    mma_bf16(acc[oh][0][nn], a[0], bb);
                    mma_bf16(acc[oh][1][nn], a[1], bb);
                }
            }
        }
        __syncthreads();
    }
#pragma unroll
    for (int oh = 0; oh < 2; oh++) {
        int o0 = oh * 128;
        if (trans) {
            __nv_bfloat16* op = out + (size_t)b * Nsp * Cch;
#pragma unroll
            for (int mm = 0; mm < 2; mm++) {
                int i_row = i0 + wm * 32 + mm * 16 + g;
#pragma unroll
                for (int nn = 0; nn < 8; nn++) {
                    int oc = o0 + wn * 64 + nn * 8 + 2 * t;
                    float bia0 = bia[oc], bia1 = bia[oc + 1];
                    __nv_bfloat162 p0 = __floats2bfloat162_rn((acc[oh][mm][nn][0] + bia0) * scale,
                                                              (acc[oh][mm][nn][1] + bia1) * scale);
                    __nv_bfloat162 p1 = __floats2bfloat162_rn((acc[oh][mm][nn][2] + bia0) * scale,
                                                              (acc[oh][mm][nn][3] + bia1) * scale);
                    *(__nv_bfloat162*)(op + (size_t)i_row * Cch + oc) = p0;
                    *(__nv_bfloat162*)(op + (size_t)(i_row + 8) * Cch + oc) = p1;
                }
            }
        } else {
            __nv_bfloat16* op = out + (size_t)b * Cch * Nsp;
#pragma unroll
            for (int mm = 0; mm < 2; mm++) {
                int o_row = o0 + wm * 32 + mm * 16 + g;
                float b0v = bia[o_row];
                float b1v = bia[o_row + 8];
#pragma unroll
                for (int nn = 0; nn < 8; nn++) {
                    int col = i0 + wn * 64 + nn * 8 + 2 * t;
                    __nv_bfloat162 p0 = __floats2bfloat162_rn(acc[oh][mm][nn][0] + b0v,
                                                              acc[oh][mm][nn][1] + b0v);
                    __nv_bfloat162 p1 = __floats2bfloat162_rn(acc[oh][mm][nn][2] + b1v,
                                                              acc[oh][mm][nn][3] + b1v);
                    *(__nv_bfloat162*)(op + (size_t)o_row * Nsp + col) = p0;
                    *(__nv_bfloat162*)(op + (size_t)(o_row + 8) * Nsp + col) = p1;
                }
            }
        }
    }
}

// ---------------- Fused flash attention (register Q + register P) ------------
// 8 warps; warp w owns rows 16w..16w+15, all 64 j, all 256 channels.
// Q fragments loaded ONCE into registers (64 regs); P re-packed in registers
// from S accumulators. Per tile LDS = K + V fragments only. 1 sync/tile.
// Fixed-base softmax (exact; |s|<1 here).
#define QSTR 264          // Q/K row stride (bf16): 528B = 33 x 16B, cf-free
#define VSTR 72           // V row stride (bf16): 144B = 9 x 16B
#define SQO  0
#define SKO  (128 * QSTR * 2)                 // 67584
#define SKBUF (64 * QSTR * 2)                 // 33792
#define SVO  (SKO + 2 * SKBUF)                // 135168
#define SVBUF (256 * VSTR * 2)                // 36864
#define ATTN_SMEM (SVO + 2 * SVBUF)           // 208896

__global__ __launch_bounds__(256, 1) void attn_kernel() {
    extern __shared__ __align__(128) char smem[];
    const uint32_t sb = smem_u32(smem);
    const int tid = threadIdx.x, lane = tid & 31, warp = tid >> 5;
    const int g = lane >> 2, qt = lane & 3;
    const int R = warp * 16;        // warp's 16 query rows
    const int b = blockIdx.y, i0 = blockIdx.x * 128;

    const __nv_bfloat16* qg = g_q + ((size_t)b * Nsp + i0) * Cch;
    const __nv_bfloat16* kg = g_k + (size_t)b * Nsp * Cch;
    const __nv_bfloat16* vg = g_v + (size_t)b * Cch * Nsp;

    // ---- prologue: Q + tile0 (group0), tile1 (group1) ----
#pragma unroll
    for (int kk = 0; kk < 16; kk++) {
        int idx = tid + kk * 256;
        int row = idx >> 5, c = (idx & 31) * 8;
        cp16(sb + SQO + (row * QSTR + c) * 2, qg + (size_t)row * Cch + c);
    }
#pragma unroll
    for (int kk = 0; kk < 8; kk++) {
        int idx = tid + kk * 256;
        int row = idx >> 5, c = (idx & 31) * 8;
        cp16(sb + SKO + (row * QSTR + c) * 2, kg + (size_t)row * Cch + c);
    }
#pragma unroll
    for (int kk = 0; kk < 8; kk++) {
        int idx = tid + kk * 256;
        int row = idx >> 3, c = (idx & 7) * 8;
        cp16(sb + SVO + (row * VSTR + c) * 2, vg + (size_t)row * Nsp + c);
    }
    CP_COMMIT;
#pragma unroll
    for (int kk = 0; kk < 8; kk++) {
        int idx = tid + kk * 256;
        int row = idx >> 5, c = (idx & 31) * 8;
        cp16(sb + SKO + SKBUF + (row * QSTR + c) * 2, kg + (size_t)(64 + row) * Cch + c);
    }
#pragma unroll
    for (int kk = 0; kk < 8; kk++) {
        int idx = tid + kk * 256;
        int row = idx >> 3, c = (idx & 7) * 8;
        cp16(sb + SVO + SVBUF + (row * VSTR + c) * 2, vg + (size_t)row * Nsp + 64 + c);
    }
    CP_COMMIT;
    CP_WAIT(1);
    __syncthreads();

    // ldmatrix lane base offsets
    const int lr = lane & 15, lk = (lane >> 4) * 8;

    // ---- Q fragments: load once into registers ----
    uint32_t qf[16][4];
    {
        const uint32_t qfb = sb + SQO + ((R + lr) * QSTR + lk) * 2;
#pragma unroll
        for (int ks = 0; ks < 16; ks++) ldsm4(qf[ks], qfb + ks * 32);
    }

    float o_acc[32][4];
#pragma unroll
    for (int nt = 0; nt < 32; nt++)
#pragma unroll
        for (int r = 0; r < 4; r++) o_acc[nt][r] = 0.f;
    float l0 = 0.f, l1 = 0.f;
    const float LOG2E = 1.4426950408889634f;

    for (int t = 0; t < 64; t++) {
        const int buf = t & 1;
        const uint32_t kfb = sb + SKO + buf * SKBUF + (lr * QSTR + lk) * 2;
        const uint32_t vfb = sb + SVO + buf * SVBUF + (lr * VSTR + lk) * 2;

        // ---- S = Q K^T : 16 rows x 64 j ----
        float s_acc[8][4];
#pragma unroll
        for (int nt = 0; nt < 8; nt++)
#pragma unroll
            for (int r = 0; r < 4; r++) s_acc[nt][r] = 0.f;
#pragma unroll
        for (int ks = 0; ks < 16; ks++) {
#pragma unroll
            for (int jg = 0; jg < 4; jg++) {
                uint32_t bb[4];
                ldsm4(bb, kfb + jg * (16 * QSTR * 2) + ks * 32);
                mma2(s_acc[2 * jg],     qf[ks], bb[0], bb[2]);
                mma2(s_acc[2 * jg + 1], qf[ks], bb[1], bb[3]);
            }
        }

        // ---- P = exp(S) in registers; accumulate l; build PV A-frags ----
        uint32_t pf[4][4];
#pragma unroll
        for (int kh = 0; kh < 4; kh++) {
#pragma unroll
            for (int hf2 = 0; hf2 < 2; hf2++) {
                int nt = 2 * kh + hf2;
                float p0 = ex2(s_acc[nt][0] * LOG2E);
                float p1 = ex2(s_acc[nt][1] * LOG2E);
                float p2 = ex2(s_acc[nt][2] * LOG2E);
                float p3 = ex2(s_acc[nt][3] * LOG2E);
                l0 += p0 + p1;
                l1 += p2 + p3;
                __nv_bfloat162 h0 = __floats2bfloat162_rn(p0, p1);
                __nv_bfloat162 h1 = __floats2bfloat162_rn(p2, p3);
                pf[kh][2 * hf2]     = *reinterpret_cast<uint32_t*>(&h0);
                pf[kh][2 * hf2 + 1] = *reinterpret_cast<uint32_t*>(&h1);
            }
        }

        // ---- O += P V^T : 16 rows x 256 channels, k = 64 j ----
#pragma unroll
        for (int kh = 0; kh < 4; kh++) {
#pragma unroll
            for (int ct = 0; ct < 16; ct++) {
                uint32_t bb[4];
                ldsm4(bb, vfb + ct * (16 * VSTR * 2) + kh * 32);
                mma2(o_acc[2 * ct],     pf[kh], bb[0], bb[2]);
                mma2(o_acc[2 * ct + 1], pf[kh], bb[1], bb[3]);
            }
        }

        CP_WAIT(0);        // tile t+1 data arrived
        __syncthreads();   // ...and visible; K/V buffers reusable

        if (t < 62) {      // issue tile t+2 into this buf
            const int tt = t + 2;
#pragma unroll
            for (int kk = 0; kk < 8; kk++) {
                int idx = tid + kk * 256;
                int row = idx >> 5, c = (idx & 31) * 8;
                cp16(sb + SKO + buf * SKBUF + (row * QSTR + c) * 2,
                     kg + (size_t)(tt * 64 + row) * Cch + c);
            }
#pragma unroll
            for (int kk = 0; kk < 8; kk++) {
                int idx = tid + kk * 256;
                int row = idx >> 3, c = (idx & 7) * 8;
                cp16(sb + SVO + buf * SVBUF + (row * VSTR + c) * 2,
                     vg + (size_t)row * Nsp + tt * 64 + c);
            }
            CP_COMMIT;
        }
    }

    // ---- l: quad reduction only (j fully warp-local) ----
    l0 += __shfl_xor_sync(0xffffffffu, l0, 1);
    l0 += __shfl_xor_sync(0xffffffffu, l0, 2);
    l1 += __shfl_xor_sync(0xffffffffu, l1, 1);
    l1 += __shfl_xor_sync(0xffffffffu, l1, 2);
    float inv0 = 1.f / l0, inv1 = 1.f / l1;

    // ---- epilogue: O / l -> g_h [b][i][c] ----
    __nv_bfloat16* h0row = g_h + ((size_t)b * Nsp + i0 + R + g) * Cch;
    __nv_bfloat16* h1row = g_h + ((size_t)b * Nsp + i0 + R + g + 8) * Cch;
#pragma unroll
    for (int nt = 0; nt < 32; nt++) {
        int col = nt * 8 + 2 * qt;
        __nv_bfloat162 a0 = __floats2bfloat162_rn(o_acc[nt][0] * inv0, o_acc[nt][1] * inv0);
        __nv_bfloat162 a1 = __floats2bfloat162_rn(o_acc[nt][2] * inv1, o_acc[nt][3] * inv1);
        *(uint32_t*)(h0row + col) = *reinterpret_cast<uint32_t*>(&a0);
        *(uint32_t*)(h1row + col) = *reinterpret_cast<uint32_t*>(&a1);
    }
}

// ---------------- Proj 1x1 conv + residual (fp32 out) ------------------------
__global__ __launch_bounds__(256) void proj_kernel(const float* __restrict__ wp,
                                                   const float* __restrict__ bp,
                                                   const float* __restrict__ xin,
                                                   float* __restrict__ out) {
    int b = blockIdx.z;
    int i0 = blockIdx.x * 128;
    int o0 = blockIdx.y * 128;

    __shared__ __align__(16) __nv_bfloat16 As[128][40];
    __shared__ __align__(16) __nv_bfloat16 Bs[128][40];

    int tid = threadIdx.x, lane = tid & 31, warp = tid >> 5;
    int g = lane >> 2, t = lane & 3;
    int wm = warp & 3, wn = warp >> 2;

    float acc[2][8][4];
#pragma unroll
    for (int mm = 0; mm < 2; mm++)
#pragma unroll
        for (int nn = 0; nn < 8; nn++)
#pragma unroll
            for (int r = 0; r < 4; r++) acc[mm][nn][r] = 0.f;

    const __nv_bfloat16* hb = g_h + (size_t)b * Nsp * Cch;   // [i][c]

    for (int k0 = 0; k0 < Cch; k0 += 32) {
#pragma unroll
        for (int idx = tid; idx < 128 * 32; idx += 256) {
            int r = idx >> 5, c = idx & 31;
            As[r][c] = __float2bfloat16_rn(wp[(size_t)(o0 + r) * Cch + k0 + c]);
        }
#pragma unroll
        for (int idx = tid; idx < 512; idx += 256) {
            int r = idx >> 2, s4 = idx & 3;
            *(uint4*)&Bs[r][s4 * 8] =
                *(const uint4*)(hb + (size_t)(i0 + r) * Cch + k0 + s4 * 8);
        }
        __syncthreads();
#pragma unroll
        for (int kk = 0; kk < 32; kk += 16) {
            uint32_t a[2][4];
#pragma unroll
            for (int mm = 0; mm < 2; mm++) {
                int r = wm * 32 + mm * 16;
                a[mm][0] = *(const uint32_t*)&As[r + g][kk + 2 * t];
                a[mm][1] = *(const uint32_t*)&As[r + g + 8][kk + 2 * t];
                a[mm][2] = *(const uint32_t*)&As[r + g][kk + 8 + 2 * t];
                a[mm][3] = *(const uint32_t*)&As[r + g + 8][kk + 8 + 2 * t];
            }
#pragma unroll
            for (int nn = 0; nn < 8; nn++) {
                int nr = wn * 64 + nn * 8 + g;
                uint32_t bb[2];
                bb[0] = *(const uint32_t*)&Bs[nr][kk + 2 * t];
                bb[1] = *(const uint32_t*)&Bs[nr][kk + 8 + 2 * t];
                mma_bf16(acc[0][nn], a[0], bb);
                mma_bf16(acc[1][nn], a[1], bb);
            }
        }
        __syncthreads();
    }

    const float* xp = xin + (size_t)b * Cch * Nsp;
    float* op = out + (size_t)b * Cch * Nsp;
#pragma unroll
    for (int mm = 0; mm < 2; mm++) {
        int o_row = o0 + wm * 32 + mm * 16 + g;
        float b0v = bp[o_row];
        float b1v = bp[o_row + 8];
#pragma unroll
        for (int nn = 0; nn < 8; nn++) {
            int col = i0 + wn * 64 + nn * 8 + 2 * t;
            size_t idx0 = (size_t)o_row * Nsp + col;
            size_t idx1 = (size_t)(o_row + 8) * Nsp + col;
            float2 x0 = *(const float2*)(xp + idx0);
            float2 x1 = *(const float2*)(xp + idx1);
            float2 r0 = make_float2(acc[mm][nn][0] + b0v + x0.x, acc[mm][nn][1] + b0v + x0.y);
            float2 r1 = make_float2(acc[mm][nn][2] + b1v + x1.x, acc[mm][nn][3] + b1v + x1.y);
            *(float2*)(op + idx0) = r0;
            *(float2*)(op + idx1) = r1;
        }
    }
}

// ---------------- launch -----------------------------------------------------
extern "C" void kernel_launch(void* const* d_in, const int* in_sizes, int n_in,
                              void* d_out, int out_size) {
    (void)in_sizes; (void)n_in; (void)out_size;
    const float* x     = (const float*)d_in[0];
    const float* gamma = (const float*)d_in[1];
    const float* beta  = (const float*)d_in[2];
    const float* wq    = (const float*)d_in[3];
    const float* bq    = (const float*)d_in[4];
    const float* wk    = (const float*)d_in[5];
    const float* bk    = (const float*)d_in[6];
    const float* wv    = (const float*)d_in[7];
    const float* bv    = (const float*)d_in[8];
    const float* wp    = (const float*)d_in[9];
    const float* bp    = (const float*)d_in[10];
    float* out = (float*)d_out;

    gn_kernel<<<Bsz * Gg, 256>>>(x, gamma, beta);
    qkv_kernel<<<dim3(Nsp / 128, 1, 12), 256>>>(wq, wk, wv, bq, bk, bv);
    cudaFuncSetAttribute(attn_kernel, cudaFuncAttributeMaxDynamicSharedMemorySize, ATTN_SMEM);
    attn_kernel<<<dim3(Nsp / 128, Bsz), 256, ATTN_SMEM>>>();
    proj_kernel<<<dim3(Nsp / 128, Cch / 128, Bsz), 256>>>(wp, bp, x, out);
}

// round 9
// speedup vs baseline: 1.0171x; 1.0171x over previous
#include <cuda_runtime.h>
#include <cuda_bf16.h>
#include <cstdint>

#define Bsz 4
#define Cch 256
#define Nsp 4096
#define Gg  32
#define CPG 8

// ---------------- scratch (static device memory; no allocations) ------------
__device__ __nv_bfloat16 g_s[Bsz * Cch * Nsp];   // [b][c][i]
__device__ __nv_bfloat16 g_q[Bsz * Nsp * Cch];   // [b][i][c] (scaled by C^-1/2)
__device__ __nv_bfloat16 g_k[Bsz * Nsp * Cch];   // [b][j][c]
__device__ __nv_bfloat16 g_v[Bsz * Cch * Nsp];   // [b][c][j]
__device__ __nv_bfloat16 g_h[Bsz * Nsp * Cch];   // [b][i][c]

// ---------------- helpers -----------------------------------------------------
__device__ __forceinline__ uint32_t smem_u32(const void* p) {
    uint32_t a;
    asm("{ .reg .u64 t; cvta.to.shared.u64 t, %1; cvt.u32.u64 %0, t; }" : "=r"(a) : "l"(p));
    return a;
}
__device__ __forceinline__ void mma_bf16(float* d, const uint32_t* a, const uint32_t* b) {
    asm volatile(
        "mma.sync.aligned.m16n8k16.row.col.f32.bf16.bf16.f32 "
        "{%0,%1,%2,%3}, {%4,%5,%6,%7}, {%8,%9}, {%0,%1,%2,%3};\n"
        : "+f"(d[0]), "+f"(d[1]), "+f"(d[2]), "+f"(d[3])
        : "r"(a[0]), "r"(a[1]), "r"(a[2]), "r"(a[3]), "r"(b[0]), "r"(b[1]));
}
__device__ __forceinline__ void mma2(float* d, const uint32_t* a, uint32_t b0, uint32_t b1) {
    asm volatile(
        "mma.sync.aligned.m16n8k16.row.col.f32.bf16.bf16.f32 "
        "{%0,%1,%2,%3}, {%4,%5,%6,%7}, {%8,%9}, {%0,%1,%2,%3};\n"
        : "+f"(d[0]), "+f"(d[1]), "+f"(d[2]), "+f"(d[3])
        : "r"(a[0]), "r"(a[1]), "r"(a[2]), "r"(a[3]), "r"(b0), "r"(b1));
}
__device__ __forceinline__ void ldsm4(uint32_t* r, uint32_t addr) {
    asm volatile("ldmatrix.sync.aligned.m8n8.x4.shared.b16 {%0,%1,%2,%3}, [%4];"
                 : "=r"(r[0]), "=r"(r[1]), "=r"(r[2]), "=r"(r[3]) : "r"(addr));
}
__device__ __forceinline__ void cp16(uint32_t saddr, const void* gaddr) {
    asm volatile("cp.async.cg.shared.global [%0], [%1], 16;" :: "r"(saddr), "l"(gaddr));
}
#define CP_COMMIT asm volatile("cp.async.commit_group;")
#define CP_WAIT(n) asm volatile("cp.async.wait_group %0;" :: "n"(n))
__device__ __forceinline__ float ex2(float a) {
    float d;
    asm("ex2.approx.ftz.f32 %0, %1;" : "=f"(d) : "f"(a));
    return d;
}

// ---------------- GroupNorm --> bf16 s ---------------------------------------
__global__ __launch_bounds__(256) void gn_kernel(const float* __restrict__ x,
                                                 const float* __restrict__ gamma,
                                                 const float* __restrict__ beta) {
    int bg = blockIdx.x;
    int b = bg >> 5;
    int g = bg & 31;
    const float4* xp = (const float4*)(x + ((size_t)b * Cch + g * CPG) * Nsp);
    const int total4 = CPG * Nsp / 4;

    float sum = 0.f, sq = 0.f;
    for (int i = threadIdx.x; i < total4; i += 256) {
        float4 v = xp[i];
        sum += v.x + v.y + v.z + v.w;
        sq  += v.x * v.x + v.y * v.y + v.z * v.z + v.w * v.w;
    }
    for (int off = 16; off > 0; off >>= 1) {
        sum += __shfl_xor_sync(0xffffffffu, sum, off);
        sq  += __shfl_xor_sync(0xffffffffu, sq, off);
    }
    __shared__ float ws[8], wq2[8];
    int warp = threadIdx.x >> 5, lane = threadIdx.x & 31;
    if (lane == 0) { ws[warp] = sum; wq2[warp] = sq; }
    __syncthreads();
    if (threadIdx.x == 0) {
        float s = 0.f, q = 0.f;
        for (int i = 0; i < 8; i++) { s += ws[i]; q += wq2[i]; }
        ws[0] = s; wq2[0] = q;
    }
    __syncthreads();
    const float invn = 1.0f / (float)(CPG * Nsp);
    float mean = ws[0] * invn;
    float var  = wq2[0] * invn - mean * mean;
    float rstd = rsqrtf(var + 1e-6f);

    __nv_bfloat162* sp = (__nv_bfloat162*)(g_s + ((size_t)b * Cch + g * CPG) * Nsp);
    for (int i = threadIdx.x; i < total4; i += 256) {
        float4 v = xp[i];
        int c = g * CPG + (i >> 10);
        float a  = rstd * gamma[c];
        float bb = beta[c] - mean * a;
        sp[2 * i]     = __floats2bfloat162_rn(v.x * a + bb, v.y * a + bb);
        sp[2 * i + 1] = __floats2bfloat162_rn(v.z * a + bb, v.w * a + bb);
    }
}

// ---------------- QKV 1x1 conv (bf16 HMMA GEMM, fused o-halves) --------------
__global__ __launch_bounds__(256) void qkv_kernel(const float* __restrict__ wq,
                                                  const float* __restrict__ wk,
                                                  const float* __restrict__ wv,
                                                  const float* __restrict__ bq,
                                                  const float* __restrict__ bk,
                                                  const float* __restrict__ bv) {
    int z = blockIdx.z;
    int b = z & 3;
    int w = z >> 2;
    const float* W   = (w == 0) ? wq : (w == 1) ? wk : wv;
    const float* bia = (w == 0) ? bq : (w == 1) ? bk : bv;
    __nv_bfloat16* out = (w == 0) ? g_q : (w == 1) ? g_k : g_v;
    float scale = (w == 0) ? 0.0625f : 1.0f;

    int i0 = blockIdx.x * 128;

    __shared__ __align__(16) __nv_bfloat16 As[256][40];  // [o][c], all 256 o
    __shared__ __align__(16) __nv_bfloat16 Bs[128][40];  // [i][c]

    int tid = threadIdx.x, lane = tid & 31, warp = tid >> 5;
    int g = lane >> 2, t = lane & 3;
    int wm = warp & 3, wn = warp >> 2;

    float acc[2][2][8][4];
#pragma unroll
    for (int oh = 0; oh < 2; oh++)
#pragma unroll
        for (int mm = 0; mm < 2; mm++)
#pragma unroll
            for (int nn = 0; nn < 8; nn++)
#pragma unroll
                for (int r = 0; r < 4; r++) acc[oh][mm][nn][r] = 0.f;

    const __nv_bfloat16* sbase = g_s + (size_t)b * Cch * Nsp + i0;
    bool trans = (w < 2);   // q,k: D[i][o]; v: D[o][i]

    for (int k0 = 0; k0 < Cch; k0 += 32) {
#pragma unroll
        for (int idx = tid; idx < 256 * 32; idx += 256) {
            int r = idx >> 5, c = idx & 31;
            As[r][c] = __float2bfloat16_rn(W[(size_t)r * Cch + k0 + c]);
        }
#pragma unroll
        for (int idx = tid; idx < 32 * 64; idx += 256) {
            int c = idx >> 6, ip = idx & 63;
            uint32_t u = *(const uint32_t*)(sbase + (size_t)(k0 + c) * Nsp + 2 * ip);
            __nv_bfloat162 h2 = *reinterpret_cast<__nv_bfloat162*>(&u);
            Bs[2 * ip][c] = h2.x;
            Bs[2 * ip + 1][c] = h2.y;
        }
        __syncthreads();
#pragma unroll
        for (int oh = 0; oh < 2; oh++) {
            const __nv_bfloat16 (*Am)[40] = trans ? Bs : (As + oh * 128);
            const __nv_bfloat16 (*Bm)[40] = trans ? (As + oh * 128) : Bs;
#pragma unroll
            for (int kk = 0; kk < 32; kk += 16) {
                uint32_t a[2][4];
#pragma unroll
                for (int mm = 0; mm < 2; mm++) {
                    int r = wm * 32 + mm * 16;
                    a[mm][0] = *(const uint32_t*)&Am[r + g][kk + 2 * t];
                    a[mm][1] = *(const uint32_t*)&Am[r + g + 8][kk + 2 * t];
                    a[mm][2] = *(const uint32_t*)&Am[r + g][kk + 8 + 2 * t];
                    a[mm][3] = *(const uint32_t*)&Am[r + g + 8][kk + 8 + 2 * t];
                }
#pragma unroll
                for (int nn = 0; nn < 8; nn++) {
                    int nr = wn * 64 + nn * 8 + g;
                    uint32_t bb[2];
                    bb[0] = *(const uint32_t*)&Bm[nr][kk + 2 * t];
                    bb[1] = *(const uint32_t*)&Bm[nr][kk + 8 + 2 * t];
                    mma_bf16(acc[oh][0][nn], a[0], bb);
                    mma_bf16(acc[oh][1][nn], a[1], bb);
                }
            }
        }
        __syncthreads();
    }
#pragma unroll
    for (int oh = 0; oh < 2; oh++) {
        int o0 = oh * 128;
        if (trans) {
            __nv_bfloat16* op = out + (size_t)b * Nsp * Cch;
#pragma unroll
            for (int mm = 0; mm < 2; mm++) {
                int i_row = i0 + wm * 32 + mm * 16 + g;
#pragma unroll
                for (int nn = 0; nn < 8; nn++) {
                    int oc = o0 + wn * 64 + nn * 8 + 2 * t;
                    float bia0 = bia[oc], bia1 = bia[oc + 1];
                    __nv_bfloat162 p0 = __floats2bfloat162_rn((acc[oh][mm][nn][0] + bia0) * scale,
                                                              (acc[oh][mm][nn][1] + bia1) * scale);
                    __nv_bfloat162 p1 = __floats2bfloat162_rn((acc[oh][mm][nn][2] + bia0) * scale,
                                                              (acc[oh][mm][nn][3] + bia1) * scale);
                    *(__nv_bfloat162*)(op + (size_t)i_row * Cch + oc) = p0;
                    *(__nv_bfloat162*)(op + (size_t)(i_row + 8) * Cch + oc) = p1;
                }
            }
        } else {
            __nv_bfloat16* op = out + (size_t)b * Cch * Nsp;
#pragma unroll
            for (int mm = 0; mm < 2; mm++) {
                int o_row = o0 + wm * 32 + mm * 16 + g;
                float b0v = bia[o_row];
                float b1v = bia[o_row + 8];
#pragma unroll
                for (int nn = 0; nn < 8; nn++) {
                    int col = i0 + wn * 64 + nn * 8 + 2 * t;
                    __nv_bfloat162 p0 = __floats2bfloat162_rn(acc[oh][mm][nn][0] + b0v,
                                                              acc[oh][mm][nn][1] + b0v);
                    __nv_bfloat162 p1 = __floats2bfloat162_rn(acc[oh][mm][nn][2] + b1v,
                                                              acc[oh][mm][nn][3] + b1v);
                    *(__nv_bfloat162*)(op + (size_t)o_row * Nsp + col) = p0;
                    *(__nv_bfloat162*)(op + (size_t)(o_row + 8) * Nsp + col) = p1;
                }
            }
        }
    }
}

// ---------------- Fused flash attention (register Q/P, half-tile pipeline) ---
// 8 warps; warp w owns rows 16w..16w+15, all 64 j, all 256 channels.
// Q fragments in registers (loaded once). Tile processed as two 32-j halves:
// S-mma(half) -> exp(half) -> PV(half). Live set per half: s_acc 16 + pf 8
// regs, keeping total under the 255 cap (no spills), and letting exp/PV of
// half 0 overlap S-mma issue of half 1. Fixed-base softmax (exact; |s|<1).
#define QSTR 264          // Q/K row stride (bf16): 528B = 33 x 16B, cf-free
#define VSTR 72           // V row stride (bf16): 144B = 9 x 16B
#define SQO  0
#define SKO  (128 * QSTR * 2)                 // 67584
#define SKBUF (64 * QSTR * 2)                 // 33792
#define SVO  (SKO + 2 * SKBUF)                // 135168
#define SVBUF (256 * VSTR * 2)                // 36864
#define ATTN_SMEM (SVO + 2 * SVBUF)           // 208896

__global__ __launch_bounds__(256, 1) void attn_kernel() {
    extern __shared__ __align__(128) char smem[];
    const uint32_t sb = smem_u32(smem);
    const int tid = threadIdx.x, lane = tid & 31, warp = tid >> 5;
    const int g = lane >> 2, qt = lane & 3;
    const int R = warp * 16;        // warp's 16 query rows
    const int b = blockIdx.y, i0 = blockIdx.x * 128;

    const __nv_bfloat16* qg = g_q + ((size_t)b * Nsp + i0) * Cch;
    const __nv_bfloat16* kg = g_k + (size_t)b * Nsp * Cch;
    const __nv_bfloat16* vg = g_v + (size_t)b * Cch * Nsp;

    // ---- prologue: Q + tile0 (group0), tile1 (group1) ----
#pragma unroll
    for (int kk = 0; kk < 16; kk++) {
        int idx = tid + kk * 256;
        int row = idx >> 5, c = (idx & 31) * 8;
        cp16(sb + SQO + (row * QSTR + c) * 2, qg + (size_t)row * Cch + c);
    }
#pragma unroll
    for (int kk = 0; kk < 8; kk++) {
        int idx = tid + kk * 256;
        int row = idx >> 5, c = (idx & 31) * 8;
        cp16(sb + SKO + (row * QSTR + c) * 2, kg + (size_t)row * Cch + c);
    }
#pragma unroll
    for (int kk = 0; kk < 8; kk++) {
        int idx = tid + kk * 256;
        int row = idx >> 3, c = (idx & 7) * 8;
        cp16(sb + SVO + (row * VSTR + c) * 2, vg + (size_t)row * Nsp + c);
    }
    CP_COMMIT;
#pragma unroll
    for (int kk = 0; kk < 8; kk++) {
        int idx = tid + kk * 256;
        int row = idx >> 5, c = (idx & 31) * 8;
        cp16(sb + SKO + SKBUF + (row * QSTR + c) * 2, kg + (size_t)(64 + row) * Cch + c);
    }
#pragma unroll
    for (int kk = 0; kk < 8; kk++) {
        int idx = tid + kk * 256;
        int row = idx >> 3, c = (idx & 7) * 8;
        cp16(sb + SVO + SVBUF + (row * VSTR + c) * 2, vg + (size_t)row * Nsp + 64 + c);
    }
    CP_COMMIT;
    CP_WAIT(1);
    __syncthreads();

    // ldmatrix lane base offsets
    const int lr = lane & 15, lk = (lane >> 4) * 8;

    // ---- Q fragments: load once into registers (64 regs) ----
    uint32_t qf[16][4];
    {
        const uint32_t qfb = sb + SQO + ((R + lr) * QSTR + lk) * 2;
#pragma unroll
        for (int ks = 0; ks < 16; ks++) ldsm4(qf[ks], qfb + ks * 32);
    }

    float o_acc[32][4];
#pragma unroll
    for (int nt = 0; nt < 32; nt++)
#pragma unroll
        for (int r = 0; r < 4; r++) o_acc[nt][r] = 0.f;
    float l0 = 0.f, l1 = 0.f;
    const float LOG2E = 1.4426950408889634f;

    for (int t = 0; t < 64; t++) {
        const int buf = t & 1;
        const uint32_t kfb = sb + SKO + buf * SKBUF + (lr * QSTR + lk) * 2;
        const uint32_t vfb = sb + SVO + buf * SVBUF + (lr * VSTR + lk) * 2;

#pragma unroll
        for (int jh = 0; jh < 2; jh++) {
            // ---- S = Q K^T : 16 rows x 32 j (this half) ----
            float s_acc[4][4];
#pragma unroll
            for (int nt = 0; nt < 4; nt++)
#pragma unroll
                for (int r = 0; r < 4; r++) s_acc[nt][r] = 0.f;
#pragma unroll
            for (int ks = 0; ks < 16; ks++) {
#pragma unroll
                for (int jg = 0; jg < 2; jg++) {
                    uint32_t bb[4];
                    ldsm4(bb, kfb + (jh * 2 + jg) * (16 * QSTR * 2) + ks * 32);
                    mma2(s_acc[2 * jg],     qf[ks], bb[0], bb[2]);
                    mma2(s_acc[2 * jg + 1], qf[ks], bb[1], bb[3]);
                }
            }

            // ---- P = exp(S) in registers; accumulate l; PV A-frags ----
            uint32_t pf[2][4];
#pragma unroll
            for (int kh = 0; kh < 2; kh++) {
#pragma unroll
                for (int hf2 = 0; hf2 < 2; hf2++) {
                    int nt = 2 * kh + hf2;
                    float p0 = ex2(s_acc[nt][0] * LOG2E);
                    float p1 = ex2(s_acc[nt][1] * LOG2E);
                    float p2 = ex2(s_acc[nt][2] * LOG2E);
                    float p3 = ex2(s_acc[nt][3] * LOG2E);
                    l0 += p0 + p1;
                    l1 += p2 + p3;
                    __nv_bfloat162 h0 = __floats2bfloat162_rn(p0, p1);
                    __nv_bfloat162 h1 = __floats2bfloat162_rn(p2, p3);
                    pf[kh][2 * hf2]     = *reinterpret_cast<uint32_t*>(&h0);
                    pf[kh][2 * hf2 + 1] = *reinterpret_cast<uint32_t*>(&h1);
                }
            }

            // ---- O += P V^T : 16 rows x 256 channels, k = this 32-j half ----
#pragma unroll
            for (int kh = 0; kh < 2; kh++) {
#pragma unroll
                for (int ct = 0; ct < 16; ct++) {
                    uint32_t bb[4];
                    ldsm4(bb, vfb + ct * (16 * VSTR * 2) + (jh * 2 + kh) * 32);
                    mma2(o_acc[2 * ct],     pf[kh], bb[0], bb[2]);
                    mma2(o_acc[2 * ct + 1], pf[kh], bb[1], bb[3]);
                }
            }
        }

        CP_WAIT(0);        // tile t+1 data arrived
        __syncthreads();   // ...and visible; K/V buffers reusable

        if (t < 62) {      // issue tile t+2 into this buf
            const int tt = t + 2;
#pragma unroll
            for (int kk = 0; kk < 8; kk++) {
                int idx = tid + kk * 256;
                int row = idx >> 5, c = (idx & 31) * 8;
                cp16(sb + SKO + buf * SKBUF + (row * QSTR + c) * 2,
                     kg + (size_t)(tt * 64 + row) * Cch + c);
            }
#pragma unroll
            for (int kk = 0; kk < 8; kk++) {
                int idx = tid + kk * 256;
                int row = idx >> 3, c = (idx & 7) * 8;
                cp16(sb + SVO + buf * SVBUF + (row * VSTR + c) * 2,
                     vg + (size_t)row * Nsp + tt * 64 + c);
            }
            CP_COMMIT;
        }
    }

    // ---- l: quad reduction only (j fully warp-local) ----
    l0 += __shfl_xor_sync(0xffffffffu, l0, 1);
    l0 += __shfl_xor_sync(0xffffffffu, l0, 2);
    l1 += __shfl_xor_sync(0xffffffffu, l1, 1);
    l1 += __shfl_xor_sync(0xffffffffu, l1, 2);
    float inv0 = 1.f / l0, inv1 = 1.f / l1;

    // ---- epilogue: O / l -> g_h [b][i][c] ----
    __nv_bfloat16* h0row = g_h + ((size_t)b * Nsp + i0 + R + g) * Cch;
    __nv_bfloat16* h1row = g_h + ((size_t)b * Nsp + i0 + R + g + 8) * Cch;
#pragma unroll
    for (int nt = 0; nt < 32; nt++) {
        int col = nt * 8 + 2 * qt;
        __nv_bfloat162 a0 = __floats2bfloat162_rn(o_acc[nt][0] * inv0, o_acc[nt][1] * inv0);
        __nv_bfloat162 a1 = __floats2bfloat162_rn(o_acc[nt][2] * inv1, o_acc[nt][3] * inv1);
        *(uint32_t*)(h0row + col) = *reinterpret_cast<uint32_t*>(&a0);
        *(uint32_t*)(h1row + col) = *reinterpret_cast<uint32_t*>(&a1);
    }
}

// ---------------- Proj 1x1 conv + residual (fp32 out) ------------------------
__global__ __launch_bounds__(256) void proj_kernel(const float* __restrict__ wp,
                                                   const float* __restrict__ bp,
                                                   const float* __restrict__ xin,
                                                   float* __restrict__ out) {
    int b = blockIdx.z;
    int i0 = blockIdx.x * 128;
    int o0 = blockIdx.y * 128;

    __shared__ __align__(16) __nv_bfloat16 As[128][40];
    __shared__ __align__(16) __nv_bfloat16 Bs[128][40];

    int tid = threadIdx.x, lane = tid & 31, warp = tid >> 5;
    int g = lane >> 2, t = lane & 3;
    int wm = warp & 3, wn = warp >> 2;

    float acc[2][8][4];
#pragma unroll
    for (int mm = 0; mm < 2; mm++)
#pragma unroll
        for (int nn = 0; nn < 8; nn++)
#pragma unroll
            for (int r = 0; r < 4; r++) acc[mm][nn][r] = 0.f;

    const __nv_bfloat16* hb = g_h + (size_t)b * Nsp * Cch;   // [i][c]

    for (int k0 = 0; k0 < Cch; k0 += 32) {
#pragma unroll
        for (int idx = tid; idx < 128 * 32; idx += 256) {
            int r = idx >> 5, c = idx & 31;
            As[r][c] = __float2bfloat16_rn(wp[(size_t)(o0 + r) * Cch + k0 + c]);
        }
#pragma unroll
        for (int idx = tid; idx < 512; idx += 256) {
            int r = idx >> 2, s4 = idx & 3;
            *(uint4*)&Bs[r][s4 * 8] =
                *(const uint4*)(hb + (size_t)(i0 + r) * Cch + k0 + s4 * 8);
        }
        __syncthreads();
#pragma unroll
        for (int kk = 0; kk < 32; kk += 16) {
            uint32_t a[2][4];
#pragma unroll
            for (int mm = 0; mm < 2; mm++) {
                int r = wm * 32 + mm * 16;
                a[mm][0] = *(const uint32_t*)&As[r + g][kk + 2 * t];
                a[mm][1] = *(const uint32_t*)&As[r + g + 8][kk + 2 * t];
                a[mm][2] = *(const uint32_t*)&As[r + g][kk + 8 + 2 * t];
                a[mm][3] = *(const uint32_t*)&As[r + g + 8][kk + 8 + 2 * t];
            }
#pragma unroll
            for (int nn = 0; nn < 8; nn++) {
                int nr = wn * 64 + nn * 8 + g;
                uint32_t bb[2];
                bb[0] = *(const uint32_t*)&Bs[nr][kk + 2 * t];
                bb[1] = *(const uint32_t*)&Bs[nr][kk + 8 + 2 * t];
                mma_bf16(acc[0][nn], a[0], bb);
                mma_bf16(acc[1][nn], a[1], bb);
            }
        }
        __syncthreads();
    }

    const float* xp = xin + (size_t)b * Cch * Nsp;
    float* op = out + (size_t)b * Cch * Nsp;
#pragma unroll
    for (int mm = 0; mm < 2; mm++) {
        int o_row = o0 + wm * 32 + mm * 16 + g;
        float b0v = bp[o_row];
        float b1v = bp[o_row + 8];
#pragma unroll
        for (int nn = 0; nn < 8; nn++) {
            int col = i0 + wn * 64 + nn * 8 + 2 * t;
            size_t idx0 = (size_t)o_row * Nsp + col;
            size_t idx1 = (size_t)(o_row + 8) * Nsp + col;
            float2 x0 = *(const float2*)(xp + idx0);
            float2 x1 = *(const float2*)(xp + idx1);
            float2 r0 = make_float2(acc[mm][nn][0] + b0v + x0.x, acc[mm][nn][1] + b0v + x0.y);
            float2 r1 = make_float2(acc[mm][nn][2] + b1v + x1.x, acc[mm][nn][3] + b1v + x1.y);
            *(float2*)(op + idx0) = r0;
            *(float2*)(op + idx1) = r1;
        }
    }
}

// ---------------- launch -----------------------------------------------------
extern "C" void kernel_launch(void* const* d_in, const int* in_sizes, int n_in,
                              void* d_out, int out_size) {
    (void)in_sizes; (void)n_in; (void)out_size;
    const float* x     = (const float*)d_in[0];
    const float* gamma = (const float*)d_in[1];
    const float* beta  = (const float*)d_in[2];
    const float* wq    = (const float*)d_in[3];
    const float* bq    = (const float*)d_in[4];
    const float* wk    = (const float*)d_in[5];
    const float* bk    = (const float*)d_in[6];
    const float* wv    = (const float*)d_in[7];
    const float* bv    = (const float*)d_in[8];
    const float* wp    = (const float*)d_in[9];
    const float* bp    = (const float*)d_in[10];
    float* out = (float*)d_out;

    gn_kernel<<<Bsz * Gg, 256>>>(x, gamma, beta);
    qkv_kernel<<<dim3(Nsp / 128, 1, 12), 256>>>(wq, wk, wv, bq, bk, bv);
    cudaFuncSetAttribute(attn_kernel, cudaFuncAttributeMaxDynamicSharedMemorySize, ATTN_SMEM);
    attn_kernel<<<dim3(Nsp / 128, Bsz), 256, ATTN_SMEM>>>();
    proj_kernel<<<dim3(Nsp / 128, Cch / 128, Bsz), 256>>>(wp, bp, x, out);
}